// round 15
// baseline (speedup 1.0000x reference)
#include <cuda_runtime.h>
#include <cstdint>

// TitansMemory B=16 L=8192 DK=DV=128 — v8: R10 skeleton (validated, 1725us)
// with MIO-count reduction. 1 row/warp, folded 3-value butterfly (5 shfl) +
// 1 r-broadcast; y written as 3 pre-scaled partials via one predicated STS
// (summed at writeback) -> 6 shfl/step vs 8. 256 CTAs x 256 thr
// (2 CTAs/SM, 16 warps/SM). kq precomputed per chunk (5-shfl 2-value fold).

#define CSTEPS 16
#define L_SEQ  8192
#define NCH    (L_SEQ / CSTEPS)
#define DK     128

using ull = unsigned long long;

__device__ __forceinline__ ull pk(float lo, float hi) {
    ull r; asm("mov.b64 %0,{%1,%2};" : "=l"(r) : "f"(lo), "f"(hi)); return r;
}
__device__ __forceinline__ float hadd2(ull p) {
    float lo, hi; asm("mov.b64 {%0,%1},%2;" : "=f"(lo), "=f"(hi) : "l"(p));
    return lo + hi;
}
__device__ __forceinline__ ull mul2(ull a, ull b) {
    ull d; asm("mul.rn.f32x2 %0,%1,%2;" : "=l"(d) : "l"(a), "l"(b)); return d;
}
__device__ __forceinline__ ull fma2(ull a, ull b, ull c) {
    ull d; asm("fma.rn.f32x2 %0,%1,%2,%3;" : "=l"(d) : "l"(a), "l"(b), "l"(c)); return d;
}
__device__ __forceinline__ unsigned su32(const void* p) {
    return (unsigned)__cvta_generic_to_shared(p);
}
__device__ __forceinline__ void cp16(unsigned s, const void* g) {
    asm volatile("cp.async.cg.shared.global [%0],[%1],16;" :: "r"(s), "l"(g));
}
__device__ __forceinline__ void cp4(unsigned s, const void* g) {
    asm volatile("cp.async.ca.shared.global [%0],[%1],4;" :: "r"(s), "l"(g));
}
__device__ __forceinline__ void cp_commit() {
    asm volatile("cp.async.commit_group;" ::: "memory");
}
__device__ __forceinline__ void cp_wait_all() {
    asm volatile("cp.async.wait_group 0;" ::: "memory");
}
__device__ __forceinline__ float dot4(float4 a, float4 b) {
    return fmaf(a.x, b.x, fmaf(a.y, b.y, fmaf(a.z, b.z, a.w * b.w)));
}

__global__ __launch_bounds__(256, 2)
void titans_kernel(const float* __restrict__ Q,
                   const float* __restrict__ K,
                   const float* __restrict__ V,
                   float* __restrict__ Y) {
    static constexpr float cCP[16] = {  // 0.98^i
        1.0f, 0.98f, 0.9604f, 0.941192f, 0.92236816f, 0.9039207968f,
        0.8858423809f, 0.8681255332f, 0.8507630226f, 0.8337477621f,
        0.8170728069f, 0.8007313508f, 0.7847167237f, 0.7690223892f,
        0.7536419414f, 0.7385691035f };
    static constexpr float cCY[16] = {  // 0.98^(i+1)
        0.98f, 0.9604f, 0.941192f, 0.92236816f, 0.9039207968f, 0.8858423809f,
        0.8681255332f, 0.8507630226f, 0.8337477621f, 0.8170728069f,
        0.8007313508f, 0.7847167237f, 0.7690223892f, 0.7536419414f,
        0.7385691035f, 0.7237977214f };
    static constexpr float cS[16] = {   // -0.1*(0.9/0.98)^(i+1)
        -0.09183673469f, -0.08433985839f, -0.07745414463f, -0.07113064017f,
        -0.06532344097f, -0.05999029968f, -0.05509252418f, -0.05059456302f,
        -0.04646378542f, -0.04267021926f, -0.03918632342f, -0.03598663375f,
        -0.03304811221f, -0.03034970510f, -0.02787207213f, -0.02559670445f };
    static constexpr float cA[16] = {   // -0.02/0.98^(i+1)
        -0.02040816327f, -0.02082465640f, -0.02124964939f, -0.02168331570f,
        -0.02212583235f, -0.02257738015f, -0.02303814301f, -0.02350830920f,
        -0.02398807061f, -0.02447762307f, -0.02497716640f, -0.02548690449f,
        -0.02600704540f, -0.02653780143f, -0.02707938921f, -0.02763202981f };
    static constexpr float cB[16] = {   // 0.2/0.9^(i+1)
        0.2222222222f, 0.2469135802f, 0.2743484225f, 0.3048315805f,
        0.3387017561f, 0.3763352846f, 0.4181503162f, 0.4646114624f,
        0.5162349582f, 0.5735943980f, 0.6373271089f, 0.7081412321f,
        0.7868235912f, 0.8742484347f, 0.9713871497f, 1.0793190552f };
    static constexpr float cYS[16] = {  // cCY[i]*cS[i]
        -0.09000000000f, -0.08099999994f, -0.07289999992f, -0.06560999987f,
        -0.05904899992f, -0.05314409988f, -0.04782968990f, -0.04304672090f,
        -0.03874204881f, -0.03486784393f, -0.03138105953f, -0.02824295358f,
        -0.02541865822f, -0.02287679240f, -0.02058911316f, -0.01853020184f };
    constexpr float C16F = 0.7237977214f;   // 0.98^16
    constexpr float B16F = 0.1853020189f;   // 0.9^16

    __shared__ float kb[2][CSTEPS][DK];
    __shared__ float qb[2][CSTEPS][DK];
    __shared__ float vT[2][8][20];           // [row][step]
    __shared__ float yb[2][CSTEPS][8][4];    // [step][row][slot 1..3]
    __shared__ float skqs[16];               // k_t.q_t

    const int tid  = threadIdx.x;
    const int w    = tid >> 5;               // warp = row 0..7
    const int lane = tid & 31;

    const int b     = blockIdx.x >> 4;       // 16 batches
    const int vbase = (blockIdx.x & 15) << 3;// 16 groups x 8 rows

    const size_t base = (size_t)b * L_SEQ * DK;
    const float* gk = K + base;
    const float* gq = Q + base;
    const float* gv = V + base;
    float*       gy = Y + base;

    // state: lane owns What[w, 4*lane..+3], mhat same
    ull W01 = 0, W23 = 0, M01 = 0, M23 = 0;

    const bool amp1 = lane & 1;
    const bool amp2 = lane & 2;
    const int  src0 = lane & 28;             // class-0 lane of own 4-group

    // ---- preload chunk 0 ----
    {
        #pragma unroll
        for (int u = 0; u < 2; ++u) {
            int id = u * 256 + tid;
            cp16(su32(&kb[0][0][0]) + id * 16, gk + id * 4);
            cp16(su32(&qb[0][0][0]) + id * 16, gq + id * 4);
        }
        if (tid < 128) {
            int i = tid >> 3, j = tid & 7;
            cp4(su32(&vT[0][j][i]), gv + (size_t)i * DK + vbase + j);
        }
        cp_commit();
        cp_wait_all();
        __syncthreads();
    }

    for (int chunk = 0; chunk < NCH; ++chunk) {
        const int cur = chunk & 1;
        const int t0  = chunk * CSTEPS;

        // ---- kq prep: warp w handles steps w and w+8 (2-value fold) ----
        {
            const float4 ka = *(const float4*)&kb[cur][w][lane << 2];
            const float4 qa = *(const float4*)&qb[cur][w][lane << 2];
            const float4 kc = *(const float4*)&kb[cur][w + 8][lane << 2];
            const float4 qc = *(const float4*)&qb[cur][w + 8][lane << 2];
            float p0 = dot4(ka, qa);
            float p1 = dot4(kc, qc);
            float s  = amp1 ? p0 : p1;
            float rc = __shfl_xor_sync(0xffffffffu, s, 1);
            float m  = (amp1 ? p1 : p0) + rc;   // even lanes: p0, odd: p1
            m += __shfl_xor_sync(0xffffffffu, m, 2);
            m += __shfl_xor_sync(0xffffffffu, m, 4);
            m += __shfl_xor_sync(0xffffffffu, m, 8);
            m += __shfl_xor_sync(0xffffffffu, m, 16);
            if (lane == 0) skqs[w] = m;
            if (lane == 1) skqs[w + 8] = m;
        }

        // stage this warp's v row (broadcast LDS.128)
        float vreg[CSTEPS];
        #pragma unroll
        for (int jj = 0; jj < 4; ++jj)
            *(float4*)&vreg[jj * 4] = *(const float4*)&vT[cur][w][jj * 4];

        // prefetch next chunk
        if (chunk + 1 < NCH) {
            const int nb = cur ^ 1;
            const size_t nt = (size_t)(t0 + CSTEPS) * DK;
            #pragma unroll
            for (int u = 0; u < 2; ++u) {
                int id = u * 256 + tid;
                cp16(su32(&kb[nb][0][0]) + id * 16, gk + nt + id * 4);
                cp16(su32(&qb[nb][0][0]) + id * 16, gq + nt + id * 4);
            }
            if (tid < 128) {
                int i = tid >> 3, j = tid & 7;
                cp4(su32(&vT[nb][j][i]), gv + nt + (size_t)i * DK + vbase + j);
            }
        }
        cp_commit();

        __syncthreads();   // skqs visible

        // stage kq values (broadcast)
        float skqreg[CSTEPS];
        #pragma unroll
        for (int jj = 0; jj < 4; ++jj)
            *(float4*)&skqreg[jj * 4] = *(const float4*)&skqs[jj * 4];

        // ---- 16 sequential steps ----
        #pragma unroll
        for (int i = 0; i < CSTEPS; ++i) {
            const float4 k4 = *(const float4*)&kb[cur][i][lane << 2];
            const float4 q4 = *(const float4*)&qb[cur][i][lane << 2];
            const ull k01 = pk(k4.x, k4.y), k23 = pk(k4.z, k4.w);
            const ull q01 = pk(q4.x, q4.y), q23 = pk(q4.z, q4.w);

            // three dots on pre-update state (per-lane partials)
            float wk = hadd2(fma2(W01, k01, mul2(W23, k23)));
            float wq = hadd2(fma2(W01, q01, mul2(W23, q23)));
            float mq = hadd2(fma2(M01, q01, mul2(M23, q23)));

            // folded butterfly (R10, validated):
            // classes (lane&3): 0 = wk, 1 = wq, 2 = mq-even, 3 = mq-odd
            float send1 = amp1 ? wk : wq;
            float recv1 = __shfl_xor_sync(0xffffffffu, send1, 1);
            float a = (amp1 ? wq : wk) + recv1;
            float send2 = amp2 ? a : mq;
            float recv2 = __shfl_xor_sync(0xffffffffu, send2, 2);
            float c = (amp2 ? mq : a) + recv2;
            c += __shfl_xor_sync(0xffffffffu, c, 4);
            c += __shfl_xor_sync(0xffffffffu, c, 8);
            c += __shfl_xor_sync(0xffffffffu, c, 16);
            const float wkall = __shfl_sync(0xffffffffu, c, src0);

            const float r  = fmaf(cCP[i], wkall, -vreg[i]);
            const float ta = cA[i] * r;
            const float tb = cB[i] * r;
            const ull a2 = pk(ta, ta);
            const ull b2 = pk(tb, tb);
            const ull s2 = pk(cS[i], cS[i]);

            // y partials: lane1 holds wq, lanes 2/3 hold mq halves.
            //   y = cCY*(wq + ta*kq) + cCY*cS*mq_e + cCY*cS*mq_o
            if (lane >= 1 && lane <= 3) {
                float val = (lane == 1)
                    ? cCY[i] * fmaf(ta, skqreg[i], c)
                    : cYS[i] * c;
                yb[cur][i][w][lane] = val;
            }

            // W += s*m + a*k ; m += b*k   (pre-update m used for W)
            W01 = fma2(s2, M01, W01); W01 = fma2(a2, k01, W01);
            M01 = fma2(b2, k01, M01);
            W23 = fma2(s2, M23, W23); W23 = fma2(a2, k23, W23);
            M23 = fma2(b2, k23, M23);
        }

        // chunk-end rescale
        {
            const ull c16 = pk(C16F, C16F);
            const ull b16 = pk(B16F, B16F);
            W01 = mul2(c16, W01); W23 = mul2(c16, W23);
            M01 = mul2(b16, M01); M23 = mul2(b16, M23);
        }

        cp_wait_all();
        __syncthreads();

        // writeback this chunk's y (sum the 3 partials)
        if (tid < 128) {
            int i = tid >> 3, j = tid & 7;
            const float4 p = *(const float4*)&yb[cur][i][j][0];
            gy[(size_t)(t0 + i) * DK + vbase + j] = p.y + p.z + p.w;
        }
    }
}

extern "C" void kernel_launch(void* const* d_in, const int* in_sizes, int n_in,
                              void* d_out, int out_size) {
    const float* Q = (const float*)d_in[0];
    const float* K = (const float*)d_in[1];
    const float* V = (const float*)d_in[2];
    float* Y = (float*)d_out;
    (void)in_sizes; (void)n_in; (void)out_size;
    titans_kernel<<<256, 256>>>(Q, K, V, Y);
}